// round 5
// baseline (speedup 1.0000x reference)
#include <cuda_runtime.h>
#include <cuda_fp16.h>

// TriPlane bilinear sampling, GB300 — round 5.
//  Sampler: 8 lanes/point, 4 points/warp. All memory instructions are
//  group-predicated so each LDG.128/STG.128 touches exactly ONE 128B line
//  (1 wavefront @ 1 cyc, no within-instruction replays).

#define NPTS   1048576
#define RES    256
#define FEAT   64
#define PLANE_ELEMS (RES * RES * FEAT)

__device__ __half g_tp16[3 * PLANE_ELEMS];

// ---------------------------------------------------------------------------
__global__ __launch_bounds__(256) void transpose_kernel(
    const float* __restrict__ p0,
    const float* __restrict__ p1,
    const float* __restrict__ p2)
{
    __shared__ float tile[FEAT][33];
    const int x0    = blockIdx.x * 32;
    const int y     = blockIdx.y;
    const int plane = blockIdx.z;
    const int tid   = threadIdx.x;

    const float* src = (plane == 0) ? p0 : (plane == 1) ? p1 : p2;

    #pragma unroll
    for (int i = 0; i < 8; i++) {
        int idx = tid + i * 256;
        int c  = idx >> 5;
        int xx = idx & 31;
        tile[c][xx] = src[c * (RES * RES) + y * RES + (x0 + xx)];
    }
    __syncthreads();

    __half* dst = g_tp16 + plane * PLANE_ELEMS;
    #pragma unroll
    for (int i = 0; i < 4; i++) {
        int idx = tid + i * 256;
        int xx = idx >> 5;
        int cp = idx & 31;
        float2 f = make_float2(tile[2 * cp][xx], tile[2 * cp + 1][xx]);
        ((half2*)(dst + ((y * RES + (x0 + xx)) * FEAT)))[cp] = __float22half2_rn(f);
    }
}

// ---------------------------------------------------------------------------
__device__ __forceinline__ void plane_setup(float u, float v,
                                            int& i00, int& i01, int& i10, int& i11,
                                            half2 w[4]) {
    float ix = (u + 1.0f) * 0.5f * (float)(RES - 1);
    float iy = (v + 1.0f) * 0.5f * (float)(RES - 1);
    float fx0 = floorf(ix);
    float fy0 = floorf(iy);

    float wx1 = ix - fx0;
    float wx0 = (fx0 + 1.0f) - ix;
    float wy1 = iy - fy0;
    float wy0 = (fy0 + 1.0f) - iy;

    // u,v in [-1,1): ix in [0,255) so x0<=254, x1=x0+1<=255 — clamps are dead.
    int x0 = (int)fx0;
    int y0 = (int)fy0;

    int r0 = y0 << 11;             // uint4 units: (y*256 + x)*8
    int c0 = x0 << 3;
    i00 = r0 + c0;
    i01 = i00 + 8;                 // x+1
    i10 = i00 + 2048;              // y+1
    i11 = i10 + 8;

    w[0] = __float2half2_rn(wx0 * wy0);
    w[1] = __float2half2_rn(wx1 * wy0);
    w[2] = __float2half2_rn(wx0 * wy1);
    w[3] = __float2half2_rn(wx1 * wy1);
}

__device__ __forceinline__ void plane_reduce(const uint4& r00, const uint4& r01,
                                             const uint4& r10, const uint4& r11,
                                             const half2 w[4], float acc[8]) {
    const half2* h00 = (const half2*)&r00;
    const half2* h01 = (const half2*)&r01;
    const half2* h10 = (const half2*)&r10;
    const half2* h11 = (const half2*)&r11;
    #pragma unroll
    for (int j = 0; j < 4; j++) {
        half2 a = __hmul2(w[0], h00[j]);
        a = __hfma2(w[1], h01[j], a);
        a = __hfma2(w[2], h10[j], a);
        a = __hfma2(w[3], h11[j], a);
        float2 f = __half22float2(a);
        acc[2 * j]     += f.x;
        acc[2 * j + 1] += f.y;
    }
}

__global__ __launch_bounds__(256) void sample_kernel(const float* __restrict__ x,
                                                     float* __restrict__ out) {
    const int gtid = blockIdx.x * blockDim.x + threadIdx.x;
    const int p    = gtid >> 3;       // point index
    const int lane = threadIdx.x & 31;
    const int grp  = lane >> 3;       // which of the 4 points in this warp
    const int sub  = lane & 7;        // channel octet within point

    const float px = __ldg(x + 3 * p + 0);
    const float py = __ldg(x + 3 * p + 1);
    const float pz = __ldg(x + 3 * p + 2);

    int a00, a01, a10, a11;
    int b00, b01, b10, b11;
    int c00, c01, c10, c11;
    half2 wa[4], wb[4], wc[4];
    plane_setup(px, py, a00, a01, a10, a11, wa);
    plane_setup(px, pz, b00, b01, b10, b11, wb);
    plane_setup(py, pz, c00, c01, c10, c11, wc);

    const uint4* base0 = (const uint4*)(g_tp16 + 0 * PLANE_ELEMS) + sub;
    const uint4* base1 = (const uint4*)(g_tp16 + 1 * PLANE_ELEMS) + sub;
    const uint4* base2 = (const uint4*)(g_tp16 + 2 * PLANE_ELEMS) + sub;

    uint4 ra0, ra1, ra2, ra3;
    uint4 rb0, rb1, rb2, rb3;
    uint4 rc0, rc1, rc2, rc3;

    // Group-predicated loads: each LDG.128 has 8 active lanes covering
    // exactly one 128B line -> single wavefront, no replays.
    #pragma unroll
    for (int g = 0; g < 4; g++) {
        if (grp == g) {
            ra0 = __ldg(base0 + a00);
            ra1 = __ldg(base0 + a01);
            ra2 = __ldg(base0 + a10);
            ra3 = __ldg(base0 + a11);
            rb0 = __ldg(base1 + b00);
            rb1 = __ldg(base1 + b01);
            rb2 = __ldg(base1 + b10);
            rb3 = __ldg(base1 + b11);
            rc0 = __ldg(base2 + c00);
            rc1 = __ldg(base2 + c01);
            rc2 = __ldg(base2 + c10);
            rc3 = __ldg(base2 + c11);
        }
    }

    float acc[8];
    #pragma unroll
    for (int i = 0; i < 8; i++) acc[i] = 0.0f;

    plane_reduce(ra0, ra1, ra2, ra3, wa, acc);
    plane_reduce(rb0, rb1, rb2, rb3, wb, acc);
    plane_reduce(rc0, rc1, rc2, rc3, wc, acc);

    const float inv3 = 1.0f / 3.0f;
    float4 o0 = make_float4(acc[0] * inv3, acc[1] * inv3, acc[2] * inv3, acc[3] * inv3);
    float4 o1 = make_float4(acc[4] * inv3, acc[5] * inv3, acc[6] * inv3, acc[7] * inv3);

    float4* dst = (float4*)(out + p * FEAT) + sub * 2;
    // Group-predicated stores: each STG.128 covers one 128B line.
    #pragma unroll
    for (int g = 0; g < 4; g++) {
        if (grp == g) {
            dst[0] = o0;
            dst[1] = o1;
        }
    }
}

// ---------------------------------------------------------------------------
extern "C" void kernel_launch(void* const* d_in, const int* in_sizes, int n_in,
                              void* d_out, int out_size) {
    const float* x        = (const float*)d_in[0];
    const float* plane_xy = (const float*)d_in[1];
    const float* plane_xz = (const float*)d_in[2];
    const float* plane_yz = (const float*)d_in[3];
    float* out = (float*)d_out;

    dim3 tgrid(RES / 32, RES, 3);
    transpose_kernel<<<tgrid, 256>>>(plane_xy, plane_xz, plane_yz);

    const int threads = 256;
    const int blocks  = (NPTS * 8) / threads;
    sample_kernel<<<blocks, threads>>>(x, out);
}

// round 8
// speedup vs baseline: 1.5571x; 1.5571x over previous
#include <cuda_runtime.h>
#include <cuda_fp16.h>
#include <cstdint>

// TriPlane bilinear sampling, GB300 — round 8 (R6 design, compile-fixed).
// Sampler: warp = 4 points. Setup computed SIMD in 8-lane groups, then per
// point the warp shuffles weights/indices from the owning group and issues
// 12 single-line LDG.32 (32 lanes x half2 = 128B = 1 line, 1 wavefront @1.0
// cyc — avoids the 2.07 cyc within-LDG replay tax of multi-line LDG.128).

#define NPTS   1048576
#define RES    256
#define FEAT   64
#define PLANE_ELEMS (RES * RES * FEAT)
#define FULLMASK 0xffffffffu

__device__ __half g_tp16[3 * PLANE_ELEMS];

__device__ __forceinline__ unsigned int h2_to_u32(half2 h) {
    return reinterpret_cast<unsigned int&>(h);
}
__device__ __forceinline__ half2 u32_to_h2(unsigned int u) {
    return reinterpret_cast<half2&>(u);
}

// ---------------------------------------------------------------------------
__global__ __launch_bounds__(256) void transpose_kernel(
    const float* __restrict__ p0,
    const float* __restrict__ p1,
    const float* __restrict__ p2)
{
    __shared__ float tile[FEAT][33];
    const int x0    = blockIdx.x * 32;
    const int y     = blockIdx.y;
    const int plane = blockIdx.z;
    const int tid   = threadIdx.x;

    const float* src = (plane == 0) ? p0 : (plane == 1) ? p1 : p2;

    #pragma unroll
    for (int i = 0; i < 8; i++) {
        int idx = tid + i * 256;
        int c  = idx >> 5;
        int xx = idx & 31;
        tile[c][xx] = src[c * (RES * RES) + y * RES + (x0 + xx)];
    }
    __syncthreads();

    __half* dst = g_tp16 + plane * PLANE_ELEMS;
    #pragma unroll
    for (int i = 0; i < 4; i++) {
        int idx = tid + i * 256;
        int xx = idx >> 5;
        int cp = idx & 31;
        float2 f = make_float2(tile[2 * cp][xx], tile[2 * cp + 1][xx]);
        ((half2*)(dst + ((y * RES + (x0 + xx)) * FEAT)))[cp] = __float22half2_rn(f);
    }
}

// ---------------------------------------------------------------------------
// Setup for one plane: texel index (y0*256+x0) and 4 splat-half2 weights
// packed as unsigned ints (for shuffling).
__device__ __forceinline__ void plane_setup(float u, float v,
                                            int& t00, unsigned int w[4]) {
    float ix = (u + 1.0f) * 0.5f * (float)(RES - 1);
    float iy = (v + 1.0f) * 0.5f * (float)(RES - 1);
    float fx0 = floorf(ix);
    float fy0 = floorf(iy);

    float wx1 = ix - fx0;
    float wx0 = (fx0 + 1.0f) - ix;
    float wy1 = iy - fy0;
    float wy0 = (fy0 + 1.0f) - iy;

    int x0 = (int)fx0;
    int y0 = (int)fy0;
    t00 = (y0 << 8) + x0;            // texel index; x in [-1,1) -> no clamps

    w[0] = h2_to_u32(__float2half2_rn(wx0 * wy0));
    w[1] = h2_to_u32(__float2half2_rn(wx1 * wy0));
    w[2] = h2_to_u32(__float2half2_rn(wx0 * wy1));
    w[3] = h2_to_u32(__float2half2_rn(wx1 * wy1));
}

// One plane for the current point: 4 single-line loads + half2 bilinear,
// result added into fp32 accumulator.
__device__ __forceinline__ void plane_gather(const half2* __restrict__ base,
                                             int t00, const unsigned int w[4],
                                             int lane, float2& acc) {
    // half2 index of texel t for this lane: t*32 + lane
    const half2* p00 = base + (t00 << 5) + lane;
    half2 v00 = __ldg(p00);            // (y0,x0)
    half2 v01 = __ldg(p00 + 32);       // (y0,x0+1)
    half2 v10 = __ldg(p00 + 8192);     // (y0+1,x0)
    half2 v11 = __ldg(p00 + 8224);     // (y0+1,x0+1)

    half2 a = __hmul2(u32_to_h2(w[0]), v00);
    a = __hfma2(u32_to_h2(w[1]), v01, a);
    a = __hfma2(u32_to_h2(w[2]), v10, a);
    a = __hfma2(u32_to_h2(w[3]), v11, a);
    float2 f = __half22float2(a);
    acc.x += f.x;
    acc.y += f.y;
}

__global__ __launch_bounds__(256) void sample_kernel(const float* __restrict__ x,
                                                     float* __restrict__ out) {
    const int gtid   = blockIdx.x * blockDim.x + threadIdx.x;
    const int warpid = gtid >> 5;
    const int lane   = threadIdx.x & 31;
    const int grp    = lane >> 3;
    const int pw     = warpid << 2;          // first of 4 points for this warp
    const int pmine  = pw + grp;             // point this group sets up

    // --- Setup phase (SIMD across the 4 groups) ---
    const float px = __ldg(x + 3 * pmine + 0);
    const float py = __ldg(x + 3 * pmine + 1);
    const float pz = __ldg(x + 3 * pmine + 2);

    int tA, tB, tC;
    unsigned int wA[4], wB[4], wC[4];
    plane_setup(px, py, tA, wA);
    plane_setup(px, pz, tB, wB);
    plane_setup(py, pz, tC, wC);

    const half2* base0 = (const half2*)(g_tp16 + 0 * PLANE_ELEMS);
    const half2* base1 = (const half2*)(g_tp16 + 1 * PLANE_ELEMS);
    const half2* base2 = (const half2*)(g_tp16 + 2 * PLANE_ELEMS);

    float2 acc[4];

    // --- Gather phase: whole warp works one point at a time ---
    #pragma unroll
    for (int g = 0; g < 4; g++) {
        const int src = g << 3;
        int gA = __shfl_sync(FULLMASK, tA, src);
        int gB = __shfl_sync(FULLMASK, tB, src);
        int gC = __shfl_sync(FULLMASK, tC, src);
        unsigned int vA[4], vB[4], vC[4];
        #pragma unroll
        for (int j = 0; j < 4; j++) {
            vA[j] = __shfl_sync(FULLMASK, wA[j], src);
            vB[j] = __shfl_sync(FULLMASK, wB[j], src);
            vC[j] = __shfl_sync(FULLMASK, wC[j], src);
        }
        float2 a = make_float2(0.0f, 0.0f);
        plane_gather(base0, gA, vA, lane, a);
        plane_gather(base1, gB, vB, lane, a);
        plane_gather(base2, gC, vC, lane, a);
        acc[g] = a;
    }

    // --- Store: lane owns channels {2*lane, 2*lane+1} of each of 4 points ---
    const float inv3 = 1.0f / 3.0f;
    #pragma unroll
    for (int g = 0; g < 4; g++) {
        float2 o = make_float2(acc[g].x * inv3, acc[g].y * inv3);
        ((float2*)(out + (pw + g) * FEAT))[lane] = o;
    }
}

// ---------------------------------------------------------------------------
extern "C" void kernel_launch(void* const* d_in, const int* in_sizes, int n_in,
                              void* d_out, int out_size) {
    const float* x        = (const float*)d_in[0];
    const float* plane_xy = (const float*)d_in[1];
    const float* plane_xz = (const float*)d_in[2];
    const float* plane_yz = (const float*)d_in[3];
    float* out = (float*)d_out;

    dim3 tgrid(RES / 32, RES, 3);
    transpose_kernel<<<tgrid, 256>>>(plane_xy, plane_xz, plane_yz);

    const int threads = 256;
    const int blocks  = (NPTS * 8) / threads;   // warp = 4 points
    sample_kernel<<<blocks, threads>>>(x, out);
}

// round 9
// speedup vs baseline: 1.8025x; 1.1576x over previous
#include <cuda_runtime.h>
#include <cuda_fp16.h>
#include <cstdint>

// TriPlane bilinear sampling, GB300 — round 9.
// R3 structure (sequential per-plane, 4 LDG.128 in flight), half2 accumulation
// end-to-end, minimal registers, launch_bounds(256,7) for ~87% occupancy.

#define NPTS   1048576
#define RES    256
#define FEAT   64
#define PLANE_ELEMS (RES * RES * FEAT)

__device__ __half g_tp16[3 * PLANE_ELEMS];

// ---------------------------------------------------------------------------
__global__ __launch_bounds__(256) void transpose_kernel(
    const float* __restrict__ p0,
    const float* __restrict__ p1,
    const float* __restrict__ p2)
{
    __shared__ float tile[FEAT][33];
    const int x0    = blockIdx.x * 32;
    const int y     = blockIdx.y;
    const int plane = blockIdx.z;
    const int tid   = threadIdx.x;

    const float* src = (plane == 0) ? p0 : (plane == 1) ? p1 : p2;

    #pragma unroll
    for (int i = 0; i < 8; i++) {
        int idx = tid + i * 256;
        int c  = idx >> 5;
        int xx = idx & 31;
        tile[c][xx] = src[c * (RES * RES) + y * RES + (x0 + xx)];
    }
    __syncthreads();

    __half* dst = g_tp16 + plane * PLANE_ELEMS;
    #pragma unroll
    for (int i = 0; i < 4; i++) {
        int idx = tid + i * 256;
        int xx = idx >> 5;
        int cp = idx & 31;
        float2 f = make_float2(tile[2 * cp][xx], tile[2 * cp + 1][xx]);
        ((half2*)(dst + ((y * RES + (x0 + xx)) * FEAT)))[cp] = __float22half2_rn(f);
    }
}

// ---------------------------------------------------------------------------
// One plane: compute weights + single texel index, 4 LDG.128, HFMA2 into acc.
__device__ __forceinline__ void sample_plane(const uint4* __restrict__ base,
                                             float u, float v,
                                             half2 acc[4]) {
    float ix = (u + 1.0f) * 0.5f * (float)(RES - 1);
    float iy = (v + 1.0f) * 0.5f * (float)(RES - 1);
    float fx0 = floorf(ix);
    float fy0 = floorf(iy);

    float wx1 = ix - fx0;
    float wx0 = (fx0 + 1.0f) - ix;
    float wy1 = iy - fy0;
    float wy0 = (fy0 + 1.0f) - iy;

    // u,v in [-1,1): ix in [0,255), so x0 <= 254 and x0+1 <= 255 — no clamps.
    int x0 = (int)fx0;
    int y0 = (int)fy0;

    // uint4 offset of texel (y0,x0): (y0*256 + x0) * 8
    const uint4* q = base + ((y0 << 11) + (x0 << 3));
    uint4 r00 = __ldg(q);
    uint4 r01 = __ldg(q + 8);       // x+1
    uint4 r10 = __ldg(q + 2048);    // y+1
    uint4 r11 = __ldg(q + 2056);    // x+1, y+1

    half2 w00 = __float2half2_rn(wx0 * wy0);
    half2 w01 = __float2half2_rn(wx1 * wy0);
    half2 w10 = __float2half2_rn(wx0 * wy1);
    half2 w11 = __float2half2_rn(wx1 * wy1);

    const half2* h00 = (const half2*)&r00;
    const half2* h01 = (const half2*)&r01;
    const half2* h10 = (const half2*)&r10;
    const half2* h11 = (const half2*)&r11;

    #pragma unroll
    for (int j = 0; j < 4; j++) {
        half2 a = acc[j];
        a = __hfma2(w00, h00[j], a);
        a = __hfma2(w01, h01[j], a);
        a = __hfma2(w10, h10[j], a);
        a = __hfma2(w11, h11[j], a);
        acc[j] = a;
    }
}

__global__ __launch_bounds__(256, 7) void sample_kernel(const float* __restrict__ x,
                                                        float* __restrict__ out) {
    const int gtid = blockIdx.x * blockDim.x + threadIdx.x;
    const int p    = gtid >> 3;       // point index (8 lanes/point)
    const int sub  = gtid & 7;        // channel octet

    const float px = __ldg(x + 3 * p + 0);
    const float py = __ldg(x + 3 * p + 1);
    const float pz = __ldg(x + 3 * p + 2);

    half2 acc[4];
    #pragma unroll
    for (int i = 0; i < 4; i++) acc[i] = __float2half2_rn(0.0f);

    const uint4* base0 = (const uint4*)(g_tp16 + 0 * PLANE_ELEMS) + sub;
    const uint4* base1 = (const uint4*)(g_tp16 + 1 * PLANE_ELEMS) + sub;
    const uint4* base2 = (const uint4*)(g_tp16 + 2 * PLANE_ELEMS) + sub;

    sample_plane(base0, px, py, acc);
    sample_plane(base1, px, pz, acc);
    sample_plane(base2, py, pz, acc);

    const float inv3 = 1.0f / 3.0f;
    float2 f0 = __half22float2(acc[0]);
    float2 f1 = __half22float2(acc[1]);
    float2 f2 = __half22float2(acc[2]);
    float2 f3 = __half22float2(acc[3]);
    float4 o0 = make_float4(f0.x * inv3, f0.y * inv3, f1.x * inv3, f1.y * inv3);
    float4 o1 = make_float4(f2.x * inv3, f2.y * inv3, f3.x * inv3, f3.y * inv3);
    float4* dst = (float4*)(out + p * FEAT) + sub * 2;
    dst[0] = o0;
    dst[1] = o1;
}

// ---------------------------------------------------------------------------
extern "C" void kernel_launch(void* const* d_in, const int* in_sizes, int n_in,
                              void* d_out, int out_size) {
    const float* x        = (const float*)d_in[0];
    const float* plane_xy = (const float*)d_in[1];
    const float* plane_xz = (const float*)d_in[2];
    const float* plane_yz = (const float*)d_in[3];
    float* out = (float*)d_out;

    dim3 tgrid(RES / 32, RES, 3);
    transpose_kernel<<<tgrid, 256>>>(plane_xy, plane_xz, plane_yz);

    const int threads = 256;
    const int blocks  = (NPTS * 8) / threads;
    sample_kernel<<<blocks, threads>>>(x, out);
}

// round 10
// speedup vs baseline: 1.8699x; 1.0374x over previous
#include <cuda_runtime.h>
#include <cuda_fp16.h>
#include <cstdint>

// TriPlane bilinear sampling, GB300 — round 10.
// Best-of: R4's 12 upfront LDG.128 (max MLP) + R9's half2 accumulation
// (minimal register/instruction footprint). 8 lanes/point.

#define NPTS   1048576
#define RES    256
#define FEAT   64
#define PLANE_ELEMS (RES * RES * FEAT)

__device__ __half g_tp16[3 * PLANE_ELEMS];

// ---------------------------------------------------------------------------
__global__ __launch_bounds__(256) void transpose_kernel(
    const float* __restrict__ p0,
    const float* __restrict__ p1,
    const float* __restrict__ p2)
{
    __shared__ float tile[FEAT][33];
    const int x0    = blockIdx.x * 32;
    const int y     = blockIdx.y;
    const int plane = blockIdx.z;
    const int tid   = threadIdx.x;

    const float* src = (plane == 0) ? p0 : (plane == 1) ? p1 : p2;

    #pragma unroll
    for (int i = 0; i < 8; i++) {
        int idx = tid + i * 256;
        int c  = idx >> 5;
        int xx = idx & 31;
        tile[c][xx] = src[c * (RES * RES) + y * RES + (x0 + xx)];
    }
    __syncthreads();

    __half* dst = g_tp16 + plane * PLANE_ELEMS;
    #pragma unroll
    for (int i = 0; i < 4; i++) {
        int idx = tid + i * 256;
        int xx = idx >> 5;
        int cp = idx & 31;
        float2 f = make_float2(tile[2 * cp][xx], tile[2 * cp + 1][xx]);
        ((half2*)(dst + ((y * RES + (x0 + xx)) * FEAT)))[cp] = __float22half2_rn(f);
    }
}

// ---------------------------------------------------------------------------
__device__ __forceinline__ void plane_setup(float u, float v,
                                            int& t00, half2 w[4]) {
    float ix = (u + 1.0f) * 0.5f * (float)(RES - 1);
    float iy = (v + 1.0f) * 0.5f * (float)(RES - 1);
    float fx0 = floorf(ix);
    float fy0 = floorf(iy);

    float wx1 = ix - fx0;
    float wx0 = (fx0 + 1.0f) - ix;
    float wy1 = iy - fy0;
    float wy0 = (fy0 + 1.0f) - iy;

    int x0 = (int)fx0;               // u,v in [-1,1): no clamps needed
    int y0 = (int)fy0;
    t00 = (y0 << 11) + (x0 << 3);    // uint4 offset of texel (y0,x0)

    w[0] = __float2half2_rn(wx0 * wy0);
    w[1] = __float2half2_rn(wx1 * wy0);
    w[2] = __float2half2_rn(wx0 * wy1);
    w[3] = __float2half2_rn(wx1 * wy1);
}

__device__ __forceinline__ void plane_reduce(const uint4& r00, const uint4& r01,
                                             const uint4& r10, const uint4& r11,
                                             const half2 w[4], half2 acc[4]) {
    const half2* h00 = (const half2*)&r00;
    const half2* h01 = (const half2*)&r01;
    const half2* h10 = (const half2*)&r10;
    const half2* h11 = (const half2*)&r11;
    #pragma unroll
    for (int j = 0; j < 4; j++) {
        half2 a = acc[j];
        a = __hfma2(w[0], h00[j], a);
        a = __hfma2(w[1], h01[j], a);
        a = __hfma2(w[2], h10[j], a);
        a = __hfma2(w[3], h11[j], a);
        acc[j] = a;
    }
}

__global__ __launch_bounds__(256) void sample_kernel(const float* __restrict__ x,
                                                     float* __restrict__ out) {
    const int gtid = blockIdx.x * blockDim.x + threadIdx.x;
    const int p    = gtid >> 3;
    const int sub  = gtid & 7;

    const float px = __ldg(x + 3 * p + 0);
    const float py = __ldg(x + 3 * p + 1);
    const float pz = __ldg(x + 3 * p + 2);

    int tA, tB, tC;
    half2 wA[4], wB[4], wC[4];
    plane_setup(px, py, tA, wA);
    plane_setup(px, pz, tB, wB);
    plane_setup(py, pz, tC, wC);

    const uint4* qA = (const uint4*)(g_tp16 + 0 * PLANE_ELEMS) + sub + tA;
    const uint4* qB = (const uint4*)(g_tp16 + 1 * PLANE_ELEMS) + sub + tB;
    const uint4* qC = (const uint4*)(g_tp16 + 2 * PLANE_ELEMS) + sub + tC;

    // All 12 loads issued before any consumption (MLP = 12).
    uint4 ra0 = __ldg(qA);
    uint4 ra1 = __ldg(qA + 8);
    uint4 ra2 = __ldg(qA + 2048);
    uint4 ra3 = __ldg(qA + 2056);
    uint4 rb0 = __ldg(qB);
    uint4 rb1 = __ldg(qB + 8);
    uint4 rb2 = __ldg(qB + 2048);
    uint4 rb3 = __ldg(qB + 2056);
    uint4 rc0 = __ldg(qC);
    uint4 rc1 = __ldg(qC + 8);
    uint4 rc2 = __ldg(qC + 2048);
    uint4 rc3 = __ldg(qC + 2056);

    half2 acc[4];
    #pragma unroll
    for (int i = 0; i < 4; i++) acc[i] = __float2half2_rn(0.0f);

    plane_reduce(ra0, ra1, ra2, ra3, wA, acc);
    plane_reduce(rb0, rb1, rb2, rb3, wB, acc);
    plane_reduce(rc0, rc1, rc2, rc3, wC, acc);

    const float inv3 = 1.0f / 3.0f;
    float2 f0 = __half22float2(acc[0]);
    float2 f1 = __half22float2(acc[1]);
    float2 f2 = __half22float2(acc[2]);
    float2 f3 = __half22float2(acc[3]);
    float4 o0 = make_float4(f0.x * inv3, f0.y * inv3, f1.x * inv3, f1.y * inv3);
    float4 o1 = make_float4(f2.x * inv3, f2.y * inv3, f3.x * inv3, f3.y * inv3);
    float4* dst = (float4*)(out + p * FEAT) + sub * 2;
    dst[0] = o0;
    dst[1] = o1;
}

// ---------------------------------------------------------------------------
extern "C" void kernel_launch(void* const* d_in, const int* in_sizes, int n_in,
                              void* d_out, int out_size) {
    const float* x        = (const float*)d_in[0];
    const float* plane_xy = (const float*)d_in[1];
    const float* plane_xz = (const float*)d_in[2];
    const float* plane_yz = (const float*)d_in[3];
    float* out = (float*)d_out;

    dim3 tgrid(RES / 32, RES, 3);
    transpose_kernel<<<tgrid, 256>>>(plane_xy, plane_xz, plane_yz);

    const int threads = 256;
    const int blocks  = (NPTS * 8) / threads;
    sample_kernel<<<blocks, threads>>>(x, out);
}

// round 11
// speedup vs baseline: 2.0222x; 1.0815x over previous
#include <cuda_runtime.h>
#include <cuda_fp16.h>
#include <cstdint>

// TriPlane bilinear sampling, GB300 — round 11.
// 16 lanes/point (warp = 2 points), lane owns 4 channels (8B, LDG.64).
// Each load instruction touches exactly 2 x 128B lines (one per point) —
// probing the 1.0 + 2.07*(n-1) within-LDG replay model. 12 loads upfront,
// half2 accumulation.

#define NPTS   1048576
#define RES    256
#define FEAT   64
#define PLANE_ELEMS (RES * RES * FEAT)

__device__ __half g_tp16[3 * PLANE_ELEMS];

// ---------------------------------------------------------------------------
__global__ __launch_bounds__(256) void transpose_kernel(
    const float* __restrict__ p0,
    const float* __restrict__ p1,
    const float* __restrict__ p2)
{
    __shared__ float tile[FEAT][33];
    const int x0    = blockIdx.x * 32;
    const int y     = blockIdx.y;
    const int plane = blockIdx.z;
    const int tid   = threadIdx.x;

    const float* src = (plane == 0) ? p0 : (plane == 1) ? p1 : p2;

    #pragma unroll
    for (int i = 0; i < 8; i++) {
        int idx = tid + i * 256;
        int c  = idx >> 5;
        int xx = idx & 31;
        tile[c][xx] = src[c * (RES * RES) + y * RES + (x0 + xx)];
    }
    __syncthreads();

    __half* dst = g_tp16 + plane * PLANE_ELEMS;
    #pragma unroll
    for (int i = 0; i < 4; i++) {
        int idx = tid + i * 256;
        int xx = idx >> 5;
        int cp = idx & 31;
        float2 f = make_float2(tile[2 * cp][xx], tile[2 * cp + 1][xx]);
        ((half2*)(dst + ((y * RES + (x0 + xx)) * FEAT)))[cp] = __float22half2_rn(f);
    }
}

// ---------------------------------------------------------------------------
__device__ __forceinline__ void plane_setup(float u, float v,
                                            int& t00, half2 w[4]) {
    float ix = (u + 1.0f) * 0.5f * (float)(RES - 1);
    float iy = (v + 1.0f) * 0.5f * (float)(RES - 1);
    float fx0 = floorf(ix);
    float fy0 = floorf(iy);

    float wx1 = ix - fx0;
    float wx0 = (fx0 + 1.0f) - ix;
    float wy1 = iy - fy0;
    float wy0 = (fy0 + 1.0f) - iy;

    int x0 = (int)fx0;               // u,v in [-1,1): no clamps needed
    int y0 = (int)fy0;
    // uint2 offset of texel (y0,x0): (y0*256 + x0) * 16   (16 uint2 per texel)
    t00 = (y0 << 12) + (x0 << 4);

    w[0] = __float2half2_rn(wx0 * wy0);
    w[1] = __float2half2_rn(wx1 * wy0);
    w[2] = __float2half2_rn(wx0 * wy1);
    w[3] = __float2half2_rn(wx1 * wy1);
}

__device__ __forceinline__ void plane_reduce(const uint2& r00, const uint2& r01,
                                             const uint2& r10, const uint2& r11,
                                             const half2 w[4], half2 acc[2]) {
    const half2* h00 = (const half2*)&r00;
    const half2* h01 = (const half2*)&r01;
    const half2* h10 = (const half2*)&r10;
    const half2* h11 = (const half2*)&r11;
    #pragma unroll
    for (int j = 0; j < 2; j++) {
        half2 a = acc[j];
        a = __hfma2(w[0], h00[j], a);
        a = __hfma2(w[1], h01[j], a);
        a = __hfma2(w[2], h10[j], a);
        a = __hfma2(w[3], h11[j], a);
        acc[j] = a;
    }
}

__global__ __launch_bounds__(256) void sample_kernel(const float* __restrict__ x,
                                                     float* __restrict__ out) {
    const int gtid = blockIdx.x * blockDim.x + threadIdx.x;
    const int p    = gtid >> 4;       // point index (16 lanes/point)
    const int sub  = gtid & 15;       // 4-channel group

    const float px = __ldg(x + 3 * p + 0);
    const float py = __ldg(x + 3 * p + 1);
    const float pz = __ldg(x + 3 * p + 2);

    int tA, tB, tC;
    half2 wA[4], wB[4], wC[4];
    plane_setup(px, py, tA, wA);
    plane_setup(px, pz, tB, wB);
    plane_setup(py, pz, tC, wC);

    const uint2* qA = (const uint2*)(g_tp16 + 0 * PLANE_ELEMS) + sub + tA;
    const uint2* qB = (const uint2*)(g_tp16 + 1 * PLANE_ELEMS) + sub + tB;
    const uint2* qC = (const uint2*)(g_tp16 + 2 * PLANE_ELEMS) + sub + tC;

    // All 12 loads issued before any consumption (MLP = 12).
    // Offsets in uint2 units: x+1 -> +16, y+1 -> +4096.
    uint2 ra0 = __ldg(qA);
    uint2 ra1 = __ldg(qA + 16);
    uint2 ra2 = __ldg(qA + 4096);
    uint2 ra3 = __ldg(qA + 4112);
    uint2 rb0 = __ldg(qB);
    uint2 rb1 = __ldg(qB + 16);
    uint2 rb2 = __ldg(qB + 4096);
    uint2 rb3 = __ldg(qB + 4112);
    uint2 rc0 = __ldg(qC);
    uint2 rc1 = __ldg(qC + 16);
    uint2 rc2 = __ldg(qC + 4096);
    uint2 rc3 = __ldg(qC + 4112);

    half2 acc[2];
    acc[0] = __float2half2_rn(0.0f);
    acc[1] = __float2half2_rn(0.0f);

    plane_reduce(ra0, ra1, ra2, ra3, wA, acc);
    plane_reduce(rb0, rb1, rb2, rb3, wB, acc);
    plane_reduce(rc0, rc1, rc2, rc3, wC, acc);

    const float inv3 = 1.0f / 3.0f;
    float2 f0 = __half22float2(acc[0]);
    float2 f1 = __half22float2(acc[1]);
    float4 o = make_float4(f0.x * inv3, f0.y * inv3, f1.x * inv3, f1.y * inv3);
    ((float4*)(out + p * FEAT))[sub] = o;
}

// ---------------------------------------------------------------------------
extern "C" void kernel_launch(void* const* d_in, const int* in_sizes, int n_in,
                              void* d_out, int out_size) {
    const float* x        = (const float*)d_in[0];
    const float* plane_xy = (const float*)d_in[1];
    const float* plane_xz = (const float*)d_in[2];
    const float* plane_yz = (const float*)d_in[3];
    float* out = (float*)d_out;

    dim3 tgrid(RES / 32, RES, 3);
    transpose_kernel<<<tgrid, 256>>>(plane_xy, plane_xz, plane_yz);

    const int threads = 256;
    const int blocks  = (NPTS * 16) / threads;   // 16 lanes per point
    sample_kernel<<<blocks, threads>>>(x, out);
}